// round 15
// baseline (speedup 1.0000x reference)
#include <cuda_runtime.h>
#include <cuda_fp16.h>
#include <math.h>
#include <stdint.h>

#define C 512
#define KSEL 256
#define HW 25600
#define HH 160
#define WW 160
#define PW 162
#define EPS 1e-5f
#define NCH1 24
#define NCH3 144
#define STRIDE 40                        // halves per smem row (ldmatrix conflict-free)
#define TILEA_H (128 * STRIDE)           // A tile halves (10240 B)
#define TILEB_H (256 * STRIDE)           // B tile halves (20480 B)
#define STAGE_H (TILEA_H + TILEB_H)      // 30720 B per stage
#define DYN_SMEM (3 * STAGE_H * 2)       // 92160 B

// ---------------- device scratch ----------------
__device__ float  g_avg[C], g_maxv[C], g_scales[C];
__device__ int    g_idx[KSEL], g_pos[C];
__device__ __half g_weff[C * 768];                 // [co][k]
__device__ __half g_w2r[(size_t)NCH3 * C * 32];    // [chunk][co][32ci]
__device__ float  g_x2[(size_t)KSEL * HW];         // depthwise out
__device__ __half g_xT[(size_t)HW * 768];          // [px][k]
__device__ __half g_hpad[(size_t)PW * PW * C];     // NHWC zero-padded (border stays 0)
__device__ float  g_s2[C], g_t2[C];

// ---------------- helpers ----------------
__device__ __forceinline__ uint32_t s2u(const void* p) {
    uint32_t a;
    asm("{ .reg .u64 t; cvta.to.shared.u64 t, %1; cvt.u32.u64 %0, t; }" : "=r"(a) : "l"(p));
    return a;
}
__device__ __forceinline__ void cp16(uint32_t d, const void* s) {
    asm volatile("cp.async.cg.shared.global [%0], [%1], 16;" :: "r"(d), "l"(s));
}
#define CP_COMMIT() asm volatile("cp.async.commit_group;" ::: "memory")
#define CP_WAIT1()  asm volatile("cp.async.wait_group 1;" ::: "memory")
#define CP_WAIT0()  asm volatile("cp.async.wait_group 0;" ::: "memory")

__device__ __forceinline__ void ldsm4(uint32_t* r, uint32_t addr) {
    asm volatile("ldmatrix.sync.aligned.m8n8.x4.shared.b16 {%0,%1,%2,%3}, [%4];"
                 : "=r"(r[0]), "=r"(r[1]), "=r"(r[2]), "=r"(r[3]) : "r"(addr));
}
__device__ __forceinline__ void mma_f16(float* c, const uint32_t* a, const uint32_t* b) {
    asm volatile(
        "mma.sync.aligned.m16n8k16.row.col.f32.f16.f16.f32 "
        "{%0,%1,%2,%3}, {%4,%5,%6,%7}, {%8,%9}, {%0,%1,%2,%3};"
        : "+f"(c[0]), "+f"(c[1]), "+f"(c[2]), "+f"(c[3])
        : "r"(a[0]), "r"(a[1]), "r"(a[2]), "r"(a[3]), "r"(b[0]), "r"(b[1]));
}

// warp computes 64x64 from one 32-deep k-chunk using ldmatrix fragments
__device__ __forceinline__ void warp_mma_chunk(uint32_t sA, uint32_t sB,
                                               int mbase, int nbase, int lane,
                                               float c[4][8][4]) {
    int arow = lane & 15, acol = (lane >> 4) << 3;            // A: m16k16 tiles
    int brow = (lane & 7) + ((lane >> 4) << 3);               // B: n16k16 tiles
    int bcol = ((lane >> 3) & 1) << 3;
    #pragma unroll
    for (int k16 = 0; k16 < 2; k16++) {
        int kc = k16 << 4;
        uint32_t a[4][4], b[4][4];
        #pragma unroll
        for (int mt = 0; mt < 4; mt++)
            ldsm4(a[mt], sA + (uint32_t)(((mbase + mt * 16 + arow) * STRIDE + kc + acol) * 2));
        #pragma unroll
        for (int nh = 0; nh < 4; nh++)
            ldsm4(b[nh], sB + (uint32_t)(((nbase + nh * 16 + brow) * STRIDE + kc + bcol) * 2));
        #pragma unroll
        for (int mt = 0; mt < 4; mt++)
            #pragma unroll
            for (int nt = 0; nt < 8; nt++)
                mma_f16(c[mt][nt], a[mt], &b[nt >> 1][(nt & 1) << 1]);
    }
}

// ---------------- kernel 1: per-channel avg + max ----------------
__global__ void reduce_kernel(const float* __restrict__ x) {
    int c = blockIdx.x;
    const float* xc = x + (size_t)c * HW;
    float s = 0.f, m = -1e30f;
    for (int i = threadIdx.x; i < HW; i += blockDim.x) {
        float v = xc[i];
        s += v; m = fmaxf(m, v);
    }
    for (int o = 16; o > 0; o >>= 1) {
        s += __shfl_xor_sync(0xffffffffu, s, o);
        m = fmaxf(m, __shfl_xor_sync(0xffffffffu, m, o));
    }
    __shared__ float ws[8], wm[8];
    int wid = threadIdx.x >> 5;
    if ((threadIdx.x & 31) == 0) { ws[wid] = s; wm[wid] = m; }
    __syncthreads();
    if (threadIdx.x == 0) {
        float st = 0.f, mt = -1e30f;
        for (int i = 0; i < 8; i++) { st += ws[i]; mt = fmaxf(mt, wm[i]); }
        g_avg[c] = st / 25600.f;
        g_maxv[c] = mt;
    }
}

// ---------------- kernel 2: MLP + sigmoid + top-K selection ----------------
__global__ void mlp_select_kernel(const float* __restrict__ wfc1,
                                  const float* __restrict__ wfc2) {
    __shared__ float s_avg[C], s_max[C], s_hid[C], s_sc[C];
    __shared__ int s_sel[C];
    int t = threadIdx.x;
    s_avg[t] = g_avg[t];
    s_max[t] = g_maxv[t];
    __syncthreads();
    {
        const float* src = (t < 256) ? s_avg : s_max;
        int k = t & 255;
        const float* wr = wfc1 + (size_t)k * C;
        float acc = 0.f;
        #pragma unroll 8
        for (int c = 0; c < C; c++) acc += src[c] * wr[c];
        s_hid[t] = fmaxf(acc, 0.f);
    }
    __syncthreads();
    float acc = 0.f;
    {
        const float* wr = wfc2 + (size_t)t * 256;
        #pragma unroll 8
        for (int k = 0; k < 256; k++) acc += (s_hid[k] + s_hid[256 + k]) * wr[k];
    }
    float sc = 1.f / (1.f + expf(-acc));
    s_sc[t] = sc;
    g_scales[t] = sc;
    __syncthreads();
    int rank = 0;
    for (int j = 0; j < C; j++) {
        float sj = s_sc[j];
        rank += (sj > sc) || (sj == sc && j < t);
    }
    int sel = (rank < KSEL) ? 1 : 0;
    s_sel[t] = sel;
    __syncthreads();
    int pos = 0;
    for (int j = 0; j < t; j++) pos += s_sel[j];
    if (sel) { g_idx[pos] = t; g_pos[t] = pos; }
    else      g_pos[t] = -1;
}

// ---------------- kernel 3: bn2 fold ----------------
__global__ void bnfold_kernel(const float* __restrict__ bdc1,
                              const float* __restrict__ g2, const float* __restrict__ b2,
                              const float* __restrict__ m2, const float* __restrict__ v2) {
    int c = threadIdx.x;
    float s = g2[c] * rsqrtf(v2[c] + EPS);
    g_s2[c] = s;
    g_t2[c] = (bdc1[c] - m2[c]) * s + b2[c];
}

// ---------------- kernel 4: effective 1x1 weights [co][768] -> fp16 ----------------
__global__ void weff_kernel(const float* __restrict__ w_dc1) {
    int e = blockIdx.x * blockDim.x + threadIdx.x;
    if (e >= C * 768) return;
    int co = e / 768;
    int k  = e - co * 768;
    float v;
    if (k < C) {
        v = g_scales[k] * w_dc1[(size_t)co * 1024 + k];
        int p = g_pos[k];
        if (p >= 0) v += w_dc1[(size_t)co * 1024 + 512 + p];
    } else {
        v = w_dc1[(size_t)co * 1024 + 768 + (k - C)];
    }
    g_weff[e] = __float2half_rn(v);
}

// ---------------- kernel 5: reorder w_dc2 -> [chunk][co][32] fp16 ----------------
__global__ void w2r_kernel(const float* __restrict__ w_dc2) {
    int e = blockIdx.x * 256 + threadIdx.x;
    if (e >= NCH3 * C * 32) return;
    int j  = e & 31;
    int co = (e >> 5) & 511;
    int ch = e >> 14;
    int tap = ch >> 4, cc = ch & 15;
    int ci = cc * 32 + j;
    g_w2r[e] = __float2half_rn(w_dc2[(size_t)co * 4608 + ci * 9 + tap]);
}

// ---------------- kernel 6: depthwise 3x3 + bn1 + relu ----------------
__global__ void x2_kernel(const float* __restrict__ x,
                          const float* __restrict__ wch,
                          const float* __restrict__ g1, const float* __restrict__ b1,
                          const float* __restrict__ m1, const float* __restrict__ v1) {
    int j = blockIdx.x;
    int ch = g_idx[j];
    float s = g1[j] * rsqrtf(v1[j] + EPS);
    float sh = b1[j] - m1[j] * s;
    float w[9];
    #pragma unroll
    for (int t = 0; t < 9; t++) w[t] = wch[j * 9 + t];
    const float* xc = x + (size_t)ch * HW;
    float* oc = g_x2 + (size_t)j * HW;
    int pbase = blockIdx.y * 1024;
    for (int p = pbase + threadIdx.x; p < pbase + 1024; p += 256) {
        int y = p / WW, xx = p - y * WW;
        float acc = 0.f;
        #pragma unroll
        for (int dy = 0; dy < 3; dy++) {
            int gy = y + dy - 1;
            if (gy < 0 || gy >= HH) continue;
            #pragma unroll
            for (int dx = 0; dx < 3; dx++) {
                int gx = xx + dx - 1;
                if (gx < 0 || gx >= WW) continue;
                acc += xc[gy * WW + gx] * w[dy * 3 + dx];
            }
        }
        oc[p] = fmaxf(acc * s + sh, 0.f);
    }
}

// ---------------- kernel 7: transpose [k][p] -> xT[p][k] fp16 ----------------
__global__ void xT_kernel(const float* __restrict__ x) {
    __shared__ float t[32][33];
    int k0 = blockIdx.y * 32, p0 = blockIdx.x * 32;
    int lx = threadIdx.x & 31, ly = threadIdx.x >> 5;
    #pragma unroll
    for (int i = 0; i < 4; i++) {
        int k = k0 + ly + 8 * i;
        const float* src = (k < C) ? (x + (size_t)k * HW) : (g_x2 + (size_t)(k - C) * HW);
        t[ly + 8 * i][lx] = src[p0 + lx];
    }
    __syncthreads();
    #pragma unroll
    for (int i = 0; i < 4; i++) {
        int p = p0 + ly + 8 * i;
        g_xT[(size_t)p * 768 + k0 + lx] = __float2half_rn(t[lx][ly + 8 * i]);
    }
}

// ---------------- kernel 8: 1x1 conv (fp16 mma + ldsm) + bn2 -> hpad NHWC fp16 ----------------
__global__ __launch_bounds__(256, 1) void gemm1_kernel() {
    extern __shared__ __half dsm[];
    __shared__ float s_s2[256], s_t2[256];
    int tid = threadIdx.x, lane = tid & 31, wid = tid >> 5;
    int g = lane >> 2, q = lane & 3;
    int p0 = blockIdx.x << 7, co0 = blockIdx.y << 8;
    int mbase = (wid >> 2) * 64, nbase = (wid & 3) * 64;

    for (int i = tid; i < 256; i += 256) {
        s_s2[i] = g_s2[co0 + i];
        s_t2[i] = g_t2[co0 + i];
    }

    int r = tid >> 1, h8 = (tid & 1) * 8;
    uint32_t sdA0 = (r * STRIDE + h8) * 2, sdA1 = sdA0 + 32;
    uint32_t sdB0 = sdA0, sdB1 = sdA1;                       // rows r and r+128 for B
    uint32_t sdB2 = ((r + 128) * STRIDE + h8) * 2, sdB3 = sdB2 + 32;
    const __half* gA  = g_xT   + (size_t)(p0  + r) * 768 + h8;
    const __half* gB0 = g_weff + (size_t)(co0 + r) * 768 + h8;
    const __half* gB1 = g_weff + (size_t)(co0 + r + 128) * 768 + h8;
    uint32_t base = s2u(dsm);
    uint32_t tA[3], tB[3];
    #pragma unroll
    for (int i = 0; i < 3; i++) {
        tA[i] = base + (uint32_t)(i * STAGE_H * 2);
        tB[i] = tA[i] + TILEA_H * 2;
    }

    float c[4][8][4] = {};

    #pragma unroll
    for (int pl = 0; pl < 2; pl++) {
        int k0 = pl << 5;
        cp16(tA[pl] + sdA0, gA + k0);   cp16(tA[pl] + sdA1, gA + k0 + 16);
        cp16(tB[pl] + sdB0, gB0 + k0);  cp16(tB[pl] + sdB1, gB0 + k0 + 16);
        cp16(tB[pl] + sdB2, gB1 + k0);  cp16(tB[pl] + sdB3, gB1 + k0 + 16);
        CP_COMMIT();
    }

    int st = 0;
    for (int it = 0; it < NCH1; it++) {
        if (it == NCH1 - 1) CP_WAIT0(); else CP_WAIT1();
        __syncthreads();
        if (it + 2 < NCH1) {
            int ps = (st + 2 >= 3) ? st - 1 : st + 2;
            int k0 = (it + 2) << 5;
            cp16(tA[ps] + sdA0, gA + k0);   cp16(tA[ps] + sdA1, gA + k0 + 16);
            cp16(tB[ps] + sdB0, gB0 + k0);  cp16(tB[ps] + sdB1, gB0 + k0 + 16);
            cp16(tB[ps] + sdB2, gB1 + k0);  cp16(tB[ps] + sdB3, gB1 + k0 + 16);
            CP_COMMIT();
        }
        warp_mma_chunk(tA[st], tB[st], mbase, nbase, lane, c);
        st = (st + 1 == 3) ? 0 : st + 1;
    }

    // epilogue: bn2 -> hpad NHWC fp16
    #pragma unroll
    for (int mt = 0; mt < 4; mt++) {
        #pragma unroll
        for (int h = 0; h < 2; h++) {
            int p = p0 + mbase + mt * 16 + g + 8 * h;
            int y = p / 160, xx = p - y * 160;
            __half* orow = g_hpad + ((size_t)(y + 1) * PW + (xx + 1)) * C + co0;
            #pragma unroll
            for (int nt = 0; nt < 8; nt++) {
                int l = nbase + nt * 8 + q * 2;
                float v0 = c[mt][nt][2 * h]     * s_s2[l]     + s_t2[l];
                float v1 = c[mt][nt][2 * h + 1] * s_s2[l + 1] + s_t2[l + 1];
                *(__half2*)(orow + l) = __floats2half2_rn(v0, v1);
            }
        }
    }
}

// ---------------- kernel 9: 3x3 conv (fp16 mma + ldsm) + bias + relu -> out NCHW ----------------
__global__ __launch_bounds__(256, 1) void conv3_mma_kernel(const float* __restrict__ bias,
                                                           float* __restrict__ out) {
    extern __shared__ __half dsm[];
    __shared__ float s_b[256];
    int tid = threadIdx.x, lane = tid & 31, wid = tid >> 5;
    int g = lane >> 2, q = lane & 3;
    int p0 = blockIdx.x << 7, co0 = blockIdx.y << 8;
    int mbase = (wid >> 2) * 64, nbase = (wid & 3) * 64;

    for (int i = tid; i < 256; i += 256) s_b[i] = bias[co0 + i];

    int r = tid >> 1, h8 = (tid & 1) * 8;
    uint32_t sdA0 = (r * STRIDE + h8) * 2, sdA1 = sdA0 + 32;
    uint32_t sdB2 = ((r + 128) * STRIDE + h8) * 2, sdB3 = sdB2 + 32;
    int pA = p0 + r;
    int yA = pA / 160, xA = pA - yA * 160;
    size_t apix = ((size_t)yA * PW + xA) * C + h8;
    const __half* gB0 = g_w2r + (size_t)(co0 + r) * 32 + h8;
    const __half* gB1 = g_w2r + (size_t)(co0 + r + 128) * 32 + h8;
    uint32_t base = s2u(dsm);
    uint32_t tA[3], tB[3];
    #pragma unroll
    for (int i = 0; i < 3; i++) {
        tA[i] = base + (uint32_t)(i * STAGE_H * 2);
        tB[i] = tA[i] + TILEA_H * 2;
    }

    float c[4][8][4] = {};

    auto load_chunk = [&](int ch, int s) {
        int tap = ch >> 4;
        int dyq = tap / 3, dxq = tap - dyq * 3;
        size_t toff = ((size_t)dyq * PW + dxq) * C + ((size_t)(ch & 15) << 5);
        const __half* a = g_hpad + apix + toff;
        const __half* b0 = gB0 + ((size_t)ch << 14);
        const __half* b1 = gB1 + ((size_t)ch << 14);
        cp16(tA[s] + sdA0, a);       cp16(tA[s] + sdA1, a + 16);
        cp16(tB[s] + sdA0, b0);      cp16(tB[s] + sdA1, b0 + 16);
        cp16(tB[s] + sdB2, b1);      cp16(tB[s] + sdB3, b1 + 16);
        CP_COMMIT();
    };

    load_chunk(0, 0);
    load_chunk(1, 1);

    int st = 0;
    for (int it = 0; it < NCH3; it++) {
        if (it == NCH3 - 1) CP_WAIT0(); else CP_WAIT1();
        __syncthreads();
        if (it + 2 < NCH3) {
            int ps = (st + 2 >= 3) ? st - 1 : st + 2;
            load_chunk(it + 2, ps);
        }
        warp_mma_chunk(tA[st], tB[st], mbase, nbase, lane, c);
        st = (st + 1 == 3) ? 0 : st + 1;
    }

    // epilogue: bias + relu -> out[co][px]
    #pragma unroll
    for (int mt = 0; mt < 4; mt++) {
        #pragma unroll
        for (int h = 0; h < 2; h++) {
            int p = p0 + mbase + mt * 16 + g + 8 * h;
            #pragma unroll
            for (int nt = 0; nt < 8; nt++) {
                int l = nbase + nt * 8 + q * 2;
                int co = co0 + l;
                float v0 = c[mt][nt][2 * h]     + s_b[l];
                float v1 = c[mt][nt][2 * h + 1] + s_b[l + 1];
                out[(size_t)co * HW + p]       = fmaxf(v0, 0.f);
                out[(size_t)(co + 1) * HW + p] = fmaxf(v1, 0.f);
            }
        }
    }
}

// ---------------- launch ----------------
extern "C" void kernel_launch(void* const* d_in, const int* in_sizes, int n_in,
                              void* d_out, int out_size) {
    (void)in_sizes; (void)n_in; (void)out_size;
    const float* x      = (const float*)d_in[0];
    const float* w_fc1  = (const float*)d_in[1];
    const float* w_fc2  = (const float*)d_in[2];
    const float* w_cheap= (const float*)d_in[3];
    const float* bn1_g  = (const float*)d_in[4];
    const float* bn1_b  = (const float*)d_in[5];
    const float* bn1_m  = (const float*)d_in[6];
    const float* bn1_v  = (const float*)d_in[7];
    const float* w_dc1  = (const float*)d_in[8];
    const float* b_dc1  = (const float*)d_in[9];
    const float* bn2_g  = (const float*)d_in[10];
    const float* bn2_b  = (const float*)d_in[11];
    const float* bn2_m  = (const float*)d_in[12];
    const float* bn2_v  = (const float*)d_in[13];
    const float* w_dc2  = (const float*)d_in[14];
    const float* b_dc2  = (const float*)d_in[15];
    float* out = (float*)d_out;

    cudaFuncSetAttribute(gemm1_kernel, cudaFuncAttributeMaxDynamicSharedMemorySize, DYN_SMEM);
    cudaFuncSetAttribute(conv3_mma_kernel, cudaFuncAttributeMaxDynamicSharedMemorySize, DYN_SMEM);

    reduce_kernel<<<C, 256>>>(x);
    mlp_select_kernel<<<1, 512>>>(w_fc1, w_fc2);
    bnfold_kernel<<<1, 512>>>(b_dc1, bn2_g, bn2_b, bn2_m, bn2_v);
    weff_kernel<<<(C * 768 + 255) / 256, 256>>>(w_dc1);
    w2r_kernel<<<(NCH3 * C * 32) / 256, 256>>>(w_dc2);
    x2_kernel<<<dim3(KSEL, 25), 256>>>(x, w_cheap, bn1_g, bn1_b, bn1_m, bn1_v);
    xT_kernel<<<dim3(800, 24), 256>>>(x);
    gemm1_kernel<<<dim3(200, 2), 256, DYN_SMEM>>>();
    conv3_mma_kernel<<<dim3(200, 2), 256, DYN_SMEM>>>(b_dc2, out);
}

// round 16
// speedup vs baseline: 1.1411x; 1.1411x over previous
#include <cuda_runtime.h>
#include <cuda_fp16.h>
#include <math.h>
#include <stdint.h>

#define C 512
#define KSEL 256
#define HW 25600
#define HH 160
#define WW 160
#define PW 162
#define EPS 1e-5f
#define NCH1 24
#define NCH3 144
#define STRIDE 40                        // halves per smem row (ldmatrix conflict-free)
#define TILE_H (128 * STRIDE)            // halves per tile (10240 B)
#define NSTG 4
#define DYN_SMEM (NSTG * 2 * TILE_H * 2) // 81920 B

// ---------------- device scratch ----------------
__device__ float  g_avg[C], g_maxv[C], g_scales[C];
__device__ int    g_idx[KSEL], g_pos[C];
__device__ __half g_weff[C * 768];                 // [co][k]
__device__ __half g_w2r[(size_t)NCH3 * C * 32];    // [chunk][co][32ci]
__device__ float  g_x2[(size_t)KSEL * HW];         // depthwise out
__device__ __half g_xT[(size_t)HW * 768];          // [px][k]
__device__ __half g_hpad[(size_t)PW * PW * C];     // NHWC zero-padded (border stays 0)
__device__ float  g_s2[C], g_t2[C];

// ---------------- helpers ----------------
__device__ __forceinline__ uint32_t s2u(const void* p) {
    uint32_t a;
    asm("{ .reg .u64 t; cvta.to.shared.u64 t, %1; cvt.u32.u64 %0, t; }" : "=r"(a) : "l"(p));
    return a;
}
__device__ __forceinline__ void cp16(uint32_t d, const void* s) {
    asm volatile("cp.async.cg.shared.global [%0], [%1], 16;" :: "r"(d), "l"(s));
}
#define CP_COMMIT() asm volatile("cp.async.commit_group;" ::: "memory")
#define CP_WAIT2()  asm volatile("cp.async.wait_group 2;" ::: "memory")

__device__ __forceinline__ void ldsm4(uint32_t* r, uint32_t addr) {
    asm volatile("ldmatrix.sync.aligned.m8n8.x4.shared.b16 {%0,%1,%2,%3}, [%4];"
                 : "=r"(r[0]), "=r"(r[1]), "=r"(r[2]), "=r"(r[3]) : "r"(addr));
}
__device__ __forceinline__ void mma_f16(float* c, const uint32_t* a, const uint32_t* b) {
    asm volatile(
        "mma.sync.aligned.m16n8k16.row.col.f32.f16.f16.f32 "
        "{%0,%1,%2,%3}, {%4,%5,%6,%7}, {%8,%9}, {%0,%1,%2,%3};"
        : "+f"(c[0]), "+f"(c[1]), "+f"(c[2]), "+f"(c[3])
        : "r"(a[0]), "r"(a[1]), "r"(a[2]), "r"(a[3]), "r"(b[0]), "r"(b[1]));
}

// warp computes 64x32 from one 32-deep k-chunk using ldmatrix fragments
__device__ __forceinline__ void warp_mma_chunk(uint32_t sA, uint32_t sB,
                                               int mbase, int nbase, int lane,
                                               float c[4][4][4]) {
    int arow = lane & 15, acol = (lane >> 4) << 3;            // A: m16k16 tiles
    int brow = (lane & 7) + ((lane >> 4) << 3);               // B: n16k16 pair tiles
    int bcol = ((lane >> 3) & 1) << 3;
    #pragma unroll
    for (int k16 = 0; k16 < 2; k16++) {
        int kc = k16 << 4;
        uint32_t a[4][4], b[2][4];
        #pragma unroll
        for (int mt = 0; mt < 4; mt++)
            ldsm4(a[mt], sA + (uint32_t)(((mbase + mt * 16 + arow) * STRIDE + kc + acol) * 2));
        #pragma unroll
        for (int nh = 0; nh < 2; nh++)
            ldsm4(b[nh], sB + (uint32_t)(((nbase + nh * 16 + brow) * STRIDE + kc + bcol) * 2));
        #pragma unroll
        for (int mt = 0; mt < 4; mt++)
            #pragma unroll
            for (int nt = 0; nt < 4; nt++)
                mma_f16(c[mt][nt], a[mt], &b[nt >> 1][(nt & 1) << 1]);
    }
}

// ---------------- kernel 1: per-channel avg + max ----------------
__global__ void reduce_kernel(const float* __restrict__ x) {
    int c = blockIdx.x;
    const float* xc = x + (size_t)c * HW;
    float s = 0.f, m = -1e30f;
    for (int i = threadIdx.x; i < HW; i += blockDim.x) {
        float v = xc[i];
        s += v; m = fmaxf(m, v);
    }
    for (int o = 16; o > 0; o >>= 1) {
        s += __shfl_xor_sync(0xffffffffu, s, o);
        m = fmaxf(m, __shfl_xor_sync(0xffffffffu, m, o));
    }
    __shared__ float ws[8], wm[8];
    int wid = threadIdx.x >> 5;
    if ((threadIdx.x & 31) == 0) { ws[wid] = s; wm[wid] = m; }
    __syncthreads();
    if (threadIdx.x == 0) {
        float st = 0.f, mt = -1e30f;
        for (int i = 0; i < 8; i++) { st += ws[i]; mt = fmaxf(mt, wm[i]); }
        g_avg[c] = st / 25600.f;
        g_maxv[c] = mt;
    }
}

// ---------------- kernel 2: MLP + sigmoid + top-K selection ----------------
__global__ void mlp_select_kernel(const float* __restrict__ wfc1,
                                  const float* __restrict__ wfc2) {
    __shared__ float s_avg[C], s_max[C], s_hid[C], s_sc[C];
    __shared__ int s_sel[C];
    int t = threadIdx.x;
    s_avg[t] = g_avg[t];
    s_max[t] = g_maxv[t];
    __syncthreads();
    {
        const float* src = (t < 256) ? s_avg : s_max;
        int k = t & 255;
        const float* wr = wfc1 + (size_t)k * C;
        float acc = 0.f;
        #pragma unroll 8
        for (int c = 0; c < C; c++) acc += src[c] * wr[c];
        s_hid[t] = fmaxf(acc, 0.f);
    }
    __syncthreads();
    float acc = 0.f;
    {
        const float* wr = wfc2 + (size_t)t * 256;
        #pragma unroll 8
        for (int k = 0; k < 256; k++) acc += (s_hid[k] + s_hid[256 + k]) * wr[k];
    }
    float sc = 1.f / (1.f + expf(-acc));
    s_sc[t] = sc;
    g_scales[t] = sc;
    __syncthreads();
    int rank = 0;
    for (int j = 0; j < C; j++) {
        float sj = s_sc[j];
        rank += (sj > sc) || (sj == sc && j < t);
    }
    int sel = (rank < KSEL) ? 1 : 0;
    s_sel[t] = sel;
    __syncthreads();
    int pos = 0;
    for (int j = 0; j < t; j++) pos += s_sel[j];
    if (sel) { g_idx[pos] = t; g_pos[t] = pos; }
    else      g_pos[t] = -1;
}

// ---------------- kernel 3: bn2 fold ----------------
__global__ void bnfold_kernel(const float* __restrict__ bdc1,
                              const float* __restrict__ g2, const float* __restrict__ b2,
                              const float* __restrict__ m2, const float* __restrict__ v2) {
    int c = threadIdx.x;
    float s = g2[c] * rsqrtf(v2[c] + EPS);
    g_s2[c] = s;
    g_t2[c] = (bdc1[c] - m2[c]) * s + b2[c];
}

// ---------------- kernel 4: effective 1x1 weights [co][768] -> fp16 ----------------
__global__ void weff_kernel(const float* __restrict__ w_dc1) {
    int e = blockIdx.x * blockDim.x + threadIdx.x;
    if (e >= C * 768) return;
    int co = e / 768;
    int k  = e - co * 768;
    float v;
    if (k < C) {
        v = g_scales[k] * w_dc1[(size_t)co * 1024 + k];
        int p = g_pos[k];
        if (p >= 0) v += w_dc1[(size_t)co * 1024 + 512 + p];
    } else {
        v = w_dc1[(size_t)co * 1024 + 768 + (k - C)];
    }
    g_weff[e] = __float2half_rn(v);
}

// ---------------- kernel 5: reorder w_dc2 -> [chunk][co][32] fp16 ----------------
__global__ void w2r_kernel(const float* __restrict__ w_dc2) {
    int e = blockIdx.x * 256 + threadIdx.x;
    if (e >= NCH3 * C * 32) return;
    int j  = e & 31;
    int co = (e >> 5) & 511;
    int ch = e >> 14;
    int tap = ch >> 4, cc = ch & 15;
    int ci = cc * 32 + j;
    g_w2r[e] = __float2half_rn(w_dc2[(size_t)co * 4608 + ci * 9 + tap]);
}

// ---------------- kernel 6: depthwise 3x3 + bn1 + relu ----------------
__global__ void x2_kernel(const float* __restrict__ x,
                          const float* __restrict__ wch,
                          const float* __restrict__ g1, const float* __restrict__ b1,
                          const float* __restrict__ m1, const float* __restrict__ v1) {
    int j = blockIdx.x;
    int ch = g_idx[j];
    float s = g1[j] * rsqrtf(v1[j] + EPS);
    float sh = b1[j] - m1[j] * s;
    float w[9];
    #pragma unroll
    for (int t = 0; t < 9; t++) w[t] = wch[j * 9 + t];
    const float* xc = x + (size_t)ch * HW;
    float* oc = g_x2 + (size_t)j * HW;
    int pbase = blockIdx.y * 1024;
    for (int p = pbase + threadIdx.x; p < pbase + 1024; p += 256) {
        int y = p / WW, xx = p - y * WW;
        float acc = 0.f;
        #pragma unroll
        for (int dy = 0; dy < 3; dy++) {
            int gy = y + dy - 1;
            if (gy < 0 || gy >= HH) continue;
            #pragma unroll
            for (int dx = 0; dx < 3; dx++) {
                int gx = xx + dx - 1;
                if (gx < 0 || gx >= WW) continue;
                acc += xc[gy * WW + gx] * w[dy * 3 + dx];
            }
        }
        oc[p] = fmaxf(acc * s + sh, 0.f);
    }
}

// ---------------- kernel 7: transpose [k][p] -> xT[p][k] fp16 ----------------
__global__ void xT_kernel(const float* __restrict__ x) {
    __shared__ float t[32][33];
    int k0 = blockIdx.y * 32, p0 = blockIdx.x * 32;
    int lx = threadIdx.x & 31, ly = threadIdx.x >> 5;
    #pragma unroll
    for (int i = 0; i < 4; i++) {
        int k = k0 + ly + 8 * i;
        const float* src = (k < C) ? (x + (size_t)k * HW) : (g_x2 + (size_t)(k - C) * HW);
        t[ly + 8 * i][lx] = src[p0 + lx];
    }
    __syncthreads();
    #pragma unroll
    for (int i = 0; i < 4; i++) {
        int p = p0 + ly + 8 * i;
        g_xT[(size_t)p * 768 + k0 + lx] = __float2half_rn(t[lx][ly + 8 * i]);
    }
}

// ---------------- kernel 8: 1x1 conv (fp16 mma + ldsm) + bn2 -> hpad NHWC fp16 ----------------
__global__ __launch_bounds__(256, 2) void gemm1_kernel() {
    extern __shared__ __half dsm[];
    __shared__ float s_s2[128], s_t2[128];
    int tid = threadIdx.x, lane = tid & 31, wid = tid >> 5;
    int g = lane >> 2, q = lane & 3;
    int p0 = blockIdx.x << 7, co0 = blockIdx.y << 7;
    int mbase = (wid >> 2) * 64, nbase = (wid & 3) * 32;

    for (int i = tid; i < 128; i += 256) {
        s_s2[i] = g_s2[co0 + i];
        s_t2[i] = g_t2[co0 + i];
    }

    int r = tid >> 1, h8 = (tid & 1) * 8;
    uint32_t sd0 = (r * STRIDE + h8) * 2, sd1 = sd0 + 32;
    const __half* gA = g_xT   + (size_t)(p0  + r) * 768 + h8;
    const __half* gB = g_weff + (size_t)(co0 + r) * 768 + h8;
    uint32_t base = s2u(dsm);
    uint32_t tA[NSTG], tB[NSTG];
    #pragma unroll
    for (int i = 0; i < NSTG; i++) {
        tA[i] = base + (uint32_t)(i * 2 * TILE_H * 2);
        tB[i] = tA[i] + TILE_H * 2;
    }

    float c[4][4][4] = {};

    // prologue: chunks 0..2
    #pragma unroll
    for (int pl = 0; pl < 3; pl++) {
        int k0 = pl << 5;
        cp16(tA[pl] + sd0, gA + k0);  cp16(tA[pl] + sd1, gA + k0 + 16);
        cp16(tB[pl] + sd0, gB + k0);  cp16(tB[pl] + sd1, gB + k0 + 16);
        CP_COMMIT();
    }

    int st = 0;
    for (int it = 0; it < NCH1; it++) {
        CP_WAIT2();
        __syncthreads();
        if (it + 3 < NCH1) {
            int ps = (st + 3) & 3;
            int k0 = (it + 3) << 5;
            cp16(tA[ps] + sd0, gA + k0);  cp16(tA[ps] + sd1, gA + k0 + 16);
            cp16(tB[ps] + sd0, gB + k0);  cp16(tB[ps] + sd1, gB + k0 + 16);
        }
        CP_COMMIT();
        warp_mma_chunk(tA[st], tB[st], mbase, nbase, lane, c);
        st = (st + 1) & 3;
    }

    // epilogue: bn2 -> hpad NHWC fp16
    #pragma unroll
    for (int mt = 0; mt < 4; mt++) {
        #pragma unroll
        for (int h = 0; h < 2; h++) {
            int p = p0 + mbase + mt * 16 + g + 8 * h;
            int y = p / 160, xx = p - y * 160;
            __half* orow = g_hpad + ((size_t)(y + 1) * PW + (xx + 1)) * C + co0;
            #pragma unroll
            for (int nt = 0; nt < 4; nt++) {
                int l = nbase + nt * 8 + q * 2;
                float v0 = c[mt][nt][2 * h]     * s_s2[l]     + s_t2[l];
                float v1 = c[mt][nt][2 * h + 1] * s_s2[l + 1] + s_t2[l + 1];
                *(__half2*)(orow + l) = __floats2half2_rn(v0, v1);
            }
        }
    }
}

// ---------------- kernel 9: 3x3 conv (fp16 mma + ldsm) + bias + relu -> out NCHW ----------------
__global__ __launch_bounds__(256, 2) void conv3_mma_kernel(const float* __restrict__ bias,
                                                           float* __restrict__ out) {
    extern __shared__ __half dsm[];
    __shared__ float s_b[128];
    int tid = threadIdx.x, lane = tid & 31, wid = tid >> 5;
    int g = lane >> 2, q = lane & 3;
    int p0 = blockIdx.x << 7, co0 = blockIdx.y << 7;
    int mbase = (wid >> 2) * 64, nbase = (wid & 3) * 32;

    for (int i = tid; i < 128; i += 256) s_b[i] = bias[co0 + i];

    int r = tid >> 1, h8 = (tid & 1) * 8;
    uint32_t sd0 = (r * STRIDE + h8) * 2, sd1 = sd0 + 32;
    int pA = p0 + r;
    int yA = pA / 160, xA = pA - yA * 160;
    size_t apix = ((size_t)yA * PW + xA) * C + h8;
    const __half* gB = g_w2r + (size_t)(co0 + r) * 32 + h8;
    uint32_t base = s2u(dsm);
    uint32_t tA[NSTG], tB[NSTG];
    #pragma unroll
    for (int i = 0; i < NSTG; i++) {
        tA[i] = base + (uint32_t)(i * 2 * TILE_H * 2);
        tB[i] = tA[i] + TILE_H * 2;
    }

    float c[4][4][4] = {};

    auto load_chunk = [&](int ch, int s) {
        int tap = ch >> 4;
        int dyq = tap / 3, dxq = tap - dyq * 3;
        size_t toff = ((size_t)dyq * PW + dxq) * C + ((size_t)(ch & 15) << 5);
        const __half* a = g_hpad + apix + toff;
        const __half* b = gB + ((size_t)ch << 14);
        cp16(tA[s] + sd0, a);      cp16(tA[s] + sd1, a + 16);
        cp16(tB[s] + sd0, b);      cp16(tB[s] + sd1, b + 16);
    };

    load_chunk(0, 0); CP_COMMIT();
    load_chunk(1, 1); CP_COMMIT();
    load_chunk(2, 2); CP_COMMIT();

    int st = 0;
    for (int it = 0; it < NCH3; it++) {
        CP_WAIT2();
        __syncthreads();
        if (it + 3 < NCH3) load_chunk(it + 3, (st + 3) & 3);
        CP_COMMIT();
        warp_mma_chunk(tA[st], tB[st], mbase, nbase, lane, c);
        st = (st + 1) & 3;
    }

    // epilogue: bias + relu -> out[co][px]
    #pragma unroll
    for (int mt = 0; mt < 4; mt++) {
        #pragma unroll
        for (int h = 0; h < 2; h++) {
            int p = p0 + mbase + mt * 16 + g + 8 * h;
            #pragma unroll
            for (int nt = 0; nt < 4; nt++) {
                int l = nbase + nt * 8 + q * 2;
                int co = co0 + l;
                float v0 = c[mt][nt][2 * h]     + s_b[l];
                float v1 = c[mt][nt][2 * h + 1] + s_b[l + 1];
                out[(size_t)co * HW + p]       = fmaxf(v0, 0.f);
                out[(size_t)(co + 1) * HW + p] = fmaxf(v1, 0.f);
            }
        }
    }
}

// ---------------- launch ----------------
extern "C" void kernel_launch(void* const* d_in, const int* in_sizes, int n_in,
                              void* d_out, int out_size) {
    (void)in_sizes; (void)n_in; (void)out_size;
    const float* x      = (const float*)d_in[0];
    const float* w_fc1  = (const float*)d_in[1];
    const float* w_fc2  = (const float*)d_in[2];
    const float* w_cheap= (const float*)d_in[3];
    const float* bn1_g  = (const float*)d_in[4];
    const float* bn1_b  = (const float*)d_in[5];
    const float* bn1_m  = (const float*)d_in[6];
    const float* bn1_v  = (const float*)d_in[7];
    const float* w_dc1  = (const float*)d_in[8];
    const float* b_dc1  = (const float*)d_in[9];
    const float* bn2_g  = (const float*)d_in[10];
    const float* bn2_b  = (const float*)d_in[11];
    const float* bn2_m  = (const float*)d_in[12];
    const float* bn2_v  = (const float*)d_in[13];
    const float* w_dc2  = (const float*)d_in[14];
    const float* b_dc2  = (const float*)d_in[15];
    float* out = (float*)d_out;

    cudaFuncSetAttribute(gemm1_kernel, cudaFuncAttributeMaxDynamicSharedMemorySize, DYN_SMEM);
    cudaFuncSetAttribute(conv3_mma_kernel, cudaFuncAttributeMaxDynamicSharedMemorySize, DYN_SMEM);

    reduce_kernel<<<C, 256>>>(x);
    mlp_select_kernel<<<1, 512>>>(w_fc1, w_fc2);
    bnfold_kernel<<<1, 512>>>(b_dc1, bn2_g, bn2_b, bn2_m, bn2_v);
    weff_kernel<<<(C * 768 + 255) / 256, 256>>>(w_dc1);
    w2r_kernel<<<(NCH3 * C * 32) / 256, 256>>>(w_dc2);
    x2_kernel<<<dim3(KSEL, 25), 256>>>(x, w_cheap, bn1_g, bn1_b, bn1_m, bn1_v);
    xT_kernel<<<dim3(800, 24), 256>>>(x);
    gemm1_kernel<<<dim3(200, 4), 256, DYN_SMEM>>>();
    conv3_mma_kernel<<<dim3(200, 4), 256, DYN_SMEM>>>(b_dc2, out);
}